// round 7
// baseline (speedup 1.0000x reference)
#include <cuda_runtime.h>
#include <math.h>

#define BB 2
#define C0 64
#define DWC 128
#define HH 160
#define WW 160
#define HW (HH*WW)
#define NPIX (BB*HW)
#define HP 162
#define WP 162
#define NOUT (BB*C0*HW)
#define PS 65

// ---------------- scratch (device globals; no allocations allowed) ----------------
__device__ float g_h[(size_t)NPIX*DWC];          // pw1 output, NHWC
__device__ float g_vp[(size_t)BB*HP*WP*DWC];     // padded value tensor
__device__ float g_dw[(size_t)NPIX*DWC];         // depthwise conv output
__device__ float g_om[(size_t)NPIX*112];         // offset/mask logits
__device__ float g_s[(size_t)NPIX*DWC];          // sampled features
__device__ float g_feat[(size_t)2*NPIX*C0];      // gated features per branch; later reused for gated conv4
__device__ float g_part[400*64];                 // pooling partials
__device__ float g_scale[BB*DWC];                // SE scale
__device__ float g_ycat[(size_t)NPIX*DWC];       // concat(y_l, y_r) NHWC

extern __shared__ float smbuf[];

// ---------------- shared GEMV helpers ----------------
// weights staged [oc][CIN+1]; input staged channel-major [c][PS] (PS=65)
template<int CIN>
__device__ __forceinline__ void load_weights(const float* __restrict__ w, float* ws, int rows) {
    const int WS = CIN + 1;
    for (int idx = threadIdx.x; idx < rows * CIN; idx += 256) {
        int oc = idx / CIN, c = idx - oc * CIN;
        ws[oc * WS + c] = w[idx];
    }
}

template<int CIN>
__device__ __forceinline__ void stage_nhwc(const float* __restrict__ src, float* in_s, int base) {
    const int C4 = CIN / 4;
    for (int idx = threadIdx.x; idx < 64 * C4; idx += 256) {
        int p = idx / C4;
        int c4 = (idx - p * C4) * 4;
        float4 v = *reinterpret_cast<const float4*>(src + (size_t)(base + p) * CIN + c4);
        in_s[(c4 + 0) * PS + p] = v.x;
        in_s[(c4 + 1) * PS + p] = v.y;
        in_s[(c4 + 2) * PS + p] = v.z;
        in_s[(c4 + 3) * PS + p] = v.w;
    }
}

template<int CIN, int TN>
__device__ __forceinline__ void gemv64(const float* in_s, const float* ws, const float* bs,
                                       float (&acc)[4][TN]) {
    const int tx = threadIdx.x & 15, ty = threadIdx.x >> 4;
    const int WS = CIN + 1;
    #pragma unroll
    for (int j = 0; j < TN; j++) {
        float bv = bs[tx + 16 * j];
        #pragma unroll
        for (int i = 0; i < 4; i++) acc[i][j] = bv;
    }
    #pragma unroll 4
    for (int c = 0; c < CIN; c++) {
        float a[4];
        #pragma unroll
        for (int i = 0; i < 4; i++) a[i] = in_s[c * PS + ty * 4 + i];
        #pragma unroll
        for (int j = 0; j < TN; j++) {
            float wv = ws[(tx + 16 * j) * WS + c];
            #pragma unroll
            for (int i = 0; i < 4; i++) acc[i][j] = fmaf(a[i], wv, acc[i][j]);
        }
    }
}

// ---------------- kernel 1: LN1 + pw1 (NCHW 64 -> NHWC 128) ----------------
__global__ __launch_bounds__(256) void k_ln_pw1(const float* __restrict__ x,
                                                const float* __restrict__ g,
                                                const float* __restrict__ w,
                                                const float* __restrict__ bias) {
    float* in_s = smbuf;                // 64*PS
    float* w_s  = in_s + 64 * PS;       // 128*65
    float* b_s  = w_s + 128 * 65;       // 128
    float* g_sm = b_s + 128;            // 64
    float* stat = g_sm + 64;            // 128 (mean, rstd)
    float* red  = stat + 128;           // 512
    int t = threadIdx.x;
    int base = blockIdx.x * 64;
    int b = base / HW, hw0 = base % HW;

    load_weights<64>(w, w_s, 128);
    if (t < 128) b_s[t] = bias[t];
    if (t < 64) g_sm[t] = g[t];

    const float* xb = x + (size_t)b * C0 * HW + hw0;
    #pragma unroll
    for (int r = 0; r < 4; r++) {
        int idx = r * 256 + t;
        int c = idx >> 4;
        int p4 = (idx & 15) * 4;
        float4 v = *reinterpret_cast<const float4*>(xb + (size_t)c * HW + p4);
        in_s[c * PS + p4 + 0] = v.x;
        in_s[c * PS + p4 + 1] = v.y;
        in_s[c * PS + p4 + 2] = v.z;
        in_s[c * PS + p4 + 3] = v.w;
    }
    __syncthreads();
    {
        int p = t & 63, part = t >> 6;
        float s1 = 0.f, s2 = 0.f;
        #pragma unroll
        for (int q = 0; q < 16; q++) {
            float v = in_s[(part * 16 + q) * PS + p];
            s1 += v; s2 += v * v;
        }
        red[part * 64 + p] = s1;
        red[256 + part * 64 + p] = s2;
    }
    __syncthreads();
    if (t < 64) {
        float s1 = red[t] + red[64 + t] + red[128 + t] + red[192 + t];
        float s2 = red[256 + t] + red[320 + t] + red[384 + t] + red[448 + t];
        float m = s1 * (1.f / 64.f);
        float var = s2 * (1.f / 64.f) - m * m;
        stat[t] = m;
        stat[64 + t] = rsqrtf(var + 1e-5f);
    }
    __syncthreads();
    #pragma unroll
    for (int r = 0; r < 16; r++) {
        int idx = r * 256 + t;
        int c = idx >> 6, p = idx & 63;
        in_s[c * PS + p] = (in_s[c * PS + p] - stat[p]) * stat[64 + p] * g_sm[c];
    }
    __syncthreads();

    float acc[4][8];
    gemv64<64, 8>(in_s, w_s, b_s, acc);
    int tx = t & 15, ty = t >> 4;
    float* ho = g_h + (size_t)base * DWC;
    #pragma unroll
    for (int i = 0; i < 4; i++) {
        int p = ty * 4 + i;
        #pragma unroll
        for (int j = 0; j < 8; j++) ho[(size_t)p * DWC + tx + 16 * j] = acc[i][j];
    }
}

// ---------------- zero padded value buffer (once per launch) ----------------
__global__ void k_zero_vp() {
    size_t i = (size_t)blockIdx.x * 256 + threadIdx.x;
    size_t n4 = (size_t)BB * HP * WP * DWC / 4;
    if (i < n4) reinterpret_cast<float4*>(g_vp)[i] = make_float4(0.f, 0.f, 0.f, 0.f);
}

// ---------------- val projection 128->128, scatter into padded vp ----------------
__global__ __launch_bounds__(256) void k_val(const float* __restrict__ w,
                                             const float* __restrict__ bias) {
    float* in_s = smbuf;                 // 128*PS
    float* w_s  = in_s + 128 * PS;       // 128*129
    float* b_s  = w_s + 128 * 129;       // 128
    int t = threadIdx.x;
    int base = blockIdx.x * 64;
    load_weights<128>(w, w_s, 128);
    if (t < 128) b_s[t] = bias[t];
    stage_nhwc<128>(g_h, in_s, base);
    __syncthreads();
    float acc[4][8];
    gemv64<128, 8>(in_s, w_s, b_s, acc);
    int tx = t & 15, ty = t >> 4;
    #pragma unroll
    for (int i = 0; i < 4; i++) {
        int pix = base + ty * 4 + i;
        int b = pix / HW, hw = pix % HW;
        int y = hw / WW, x = hw % WW;
        float* vo = g_vp + ((size_t)(b * HP + y + 1) * WP + (x + 1)) * DWC;
        #pragma unroll
        for (int j = 0; j < 8; j++) vo[tx + 16 * j] = acc[i][j];
    }
}

// ---------------- depthwise 3x3 SAME ----------------
__global__ __launch_bounds__(256) void k_dwc(const float* __restrict__ w,
                                             const float* __restrict__ bias) {
    int tid = blockIdx.x * 256 + threadIdx.x;
    if (tid >= NPIX * 32) return;
    int c4 = (tid & 31) * 4;
    int pix = tid >> 5;
    int b = pix / HW, hw = pix % HW;
    int y = hw / WW, x = hw % WW;
    float4 acc = *reinterpret_cast<const float4*>(bias + c4);
    #pragma unroll
    for (int ky = 0; ky < 3; ky++) {
        int yy = y + ky - 1;
        if (yy < 0 || yy >= HH) continue;
        #pragma unroll
        for (int kx = 0; kx < 3; kx++) {
            int xx = x + kx - 1;
            if (xx < 0 || xx >= WW) continue;
            float4 v = *reinterpret_cast<const float4*>(
                g_h + ((size_t)b * HW + (size_t)yy * WW + xx) * DWC + c4);
            float4 wv = *reinterpret_cast<const float4*>(w + (ky * 3 + kx) * DWC + c4);
            acc.x = fmaf(v.x, wv.x, acc.x);
            acc.y = fmaf(v.y, wv.y, acc.y);
            acc.z = fmaf(v.z, wv.z, acc.z);
            acc.w = fmaf(v.w, wv.w, acc.w);
        }
    }
    *reinterpret_cast<float4*>(g_dw + (size_t)pix * DWC + c4) = acc;
}

// ---------------- offset/mask projection 128->112 ----------------
__global__ __launch_bounds__(256) void k_om(const float* __restrict__ w,
                                            const float* __restrict__ bias) {
    float* in_s = smbuf;                 // 128*PS
    float* w_s  = in_s + 128 * PS;       // 112*129
    float* b_s  = w_s + 112 * 129;       // 112
    int t = threadIdx.x;
    int base = blockIdx.x * 64;
    load_weights<128>(w, w_s, 112);
    if (t < 112) b_s[t] = bias[t];
    stage_nhwc<128>(g_dw, in_s, base);
    __syncthreads();
    float acc[4][7];
    gemv64<128, 7>(in_s, w_s, b_s, acc);
    int tx = t & 15, ty = t >> 4;
    #pragma unroll
    for (int i = 0; i < 4; i++) {
        int pix = base + ty * 4 + i;
        #pragma unroll
        for (int j = 0; j < 7; j++) g_om[(size_t)pix * 112 + tx + 16 * j] = acc[i][j];
    }
}

// ---------------- DCN bilinear sampling: warp per (pixel, group), lane = channel ----------------
__global__ __launch_bounds__(256) void k_sample() {
    __shared__ float som[224];
    int t = threadIdx.x;
    int base = blockIdx.x * 2;  // 2 pixels per block
    for (int i = t; i < 224; i += 256) som[i] = g_om[(size_t)base * 112 + i];
    __syncthreads();
    int wp = t >> 5, lane = t & 31;
    int pi = wp >> 2, g = wp & 3;
    int pix = base + pi;
    int b = pix / HW, hw = pix % HW;
    int y = hw / WW, x = hw % WW;
    const float* om = som + pi * 112 + g * 27;
    int gc = g * 32 + lane;
    const float* vpb = g_vp + (size_t)b * HP * WP * DWC + gc;
    float acc = 0.f;
    #pragma unroll
    for (int k = 0; k < 9; k++) {
        float offx = om[k * 3 + 0];
        float offy = om[k * 3 + 1];
        float mask = om[k * 3 + 2];
        float px = (float)(x + (k % 3)) + offx;   // = x + 1 + kx + offx
        float py = (float)(y + (k / 3)) + offy;   // = y + 1 + ky + offy
        float x0f = floorf(px), y0f = floorf(py);
        float tx = px - x0f, ty = py - y0f;
        int x0 = (int)x0f, y0 = (int)y0f;
        #pragma unroll
        for (int dy = 0; dy < 2; dy++) {
            #pragma unroll
            for (int dx = 0; dx < 2; dx++) {
                int xi = x0 + dx, yi = y0 + dy;
                float wg = (dx ? tx : 1.f - tx) * (dy ? ty : 1.f - ty);
                bool valid = (xi >= 0) & (xi < WP) & (yi >= 0) & (yi < HP);
                wg = valid ? wg * mask : 0.f;
                int xc = min(max(xi, 0), WP - 1);
                int yc = min(max(yi, 0), HP - 1);
                acc = fmaf(wg, vpb[((size_t)yc * WP + xc) * DWC], acc);
            }
        }
    }
    g_s[(size_t)pix * DWC + gc] = acc;
}

// ---------------- output projection 128->128 + SimpleGate -> 64 ----------------
__global__ __launch_bounds__(256) void k_outp_sg(const float* __restrict__ w,
                                                 const float* __restrict__ bias, int br) {
    float* in_s = smbuf;
    float* w_s  = in_s + 128 * PS;
    float* b_s  = w_s + 128 * 129;
    int t = threadIdx.x;
    int base = blockIdx.x * 64;
    load_weights<128>(w, w_s, 128);
    if (t < 128) b_s[t] = bias[t];
    stage_nhwc<128>(g_s, in_s, base);
    __syncthreads();
    float acc[4][8];
    gemv64<128, 8>(in_s, w_s, b_s, acc);
    int tx = t & 15, ty = t >> 4;
    float* fo = g_feat + (size_t)br * NPIX * C0;
    #pragma unroll
    for (int i = 0; i < 4; i++) {
        int pix = base + ty * 4 + i;
        #pragma unroll
        for (int j = 0; j < 4; j++)
            fo[(size_t)pix * C0 + tx + 16 * j] = acc[i][j] * acc[i][j + 4];
    }
}

// ---------------- pooling stage 1 ----------------
__global__ __launch_bounds__(256) void k_pool1() {
    __shared__ float red[256];
    int blk = blockIdx.x;          // (br*2+b)*100 + chunk
    int chunk = blk % 100;
    int bb = (blk / 100) & 1;
    int br = blk / 200;
    int pix0 = bb * HW + chunk * 256;
    int c = threadIdx.x & 63, sub = threadIdx.x >> 6;
    const float* f = g_feat + (size_t)br * NPIX * C0 + (size_t)(pix0 + sub * 64) * C0 + c;
    float s = 0.f;
    #pragma unroll 4
    for (int p = 0; p < 64; p++) s += f[(size_t)p * C0];
    red[threadIdx.x] = s;
    __syncthreads();
    if (sub == 0)
        g_part[blk * 64 + c] = red[c] + red[64 + c] + red[128 + c] + red[192 + c];
}

// ---------------- pooling stage 2 + SE scale ----------------
__global__ __launch_bounds__(256) void k_pool_scale(const float* __restrict__ sw,
                                                    const float* __restrict__ sb) {
    __shared__ float pooled[2 * 128];
    int t = threadIdx.x;
    int b = t >> 7, cc = t & 127;
    int br = cc >> 6, c = cc & 63;
    float s = 0.f;
    for (int ch = 0; ch < 100; ch++)
        s += g_part[((br * 2 + b) * 100 + ch) * 64 + c];
    pooled[b * 128 + cc] = s * (1.f / (float)HW);
    __syncthreads();
    float acc = sb[cc];
    #pragma unroll 4
    for (int k = 0; k < 128; k++) acc = fmaf(sw[cc * 128 + k], pooled[b * 128 + k], acc);
    g_scale[b * 128 + cc] = acc;
}

// ---------------- SE-mul + conv3 (128->64) + residuals -> y_cat ----------------
__global__ __launch_bounds__(256) void k_conv3_res(const float* __restrict__ w,
                                                   const float* __restrict__ bias,
                                                   const float* __restrict__ xl,
                                                   const float* __restrict__ xr,
                                                   const float* __restrict__ beta) {
    float* in_s = smbuf;                 // 128*PS
    float* w_s  = in_s + 128 * PS;       // 64*129
    float* b_s  = w_s + 64 * 129;        // 64
    float* sc_s = b_s + 64;              // 128
    float* bt_s = sc_s + 128;            // 64
    int t = threadIdx.x;
    int base = blockIdx.x * 64;
    int b = base / HW, hw0 = base % HW;
    load_weights<128>(w, w_s, 64);
    if (t < 64) b_s[t] = bias[t];
    if (t < 128) sc_s[t] = g_scale[b * 128 + t];
    if (t >= 128 && t < 192) bt_s[t - 128] = beta[t - 128];
    __syncthreads();
    // stage x_cat * scale, channel-major
    for (int idx = t; idx < 64 * 32; idx += 256) {
        int p = idx >> 5;
        int c4 = (idx & 31) * 4;
        int br = c4 >> 6;
        int cl = c4 & 63;
        float4 v = *reinterpret_cast<const float4*>(
            g_feat + (size_t)br * NPIX * C0 + (size_t)(base + p) * C0 + cl);
        in_s[(c4 + 0) * PS + p] = v.x * sc_s[c4 + 0];
        in_s[(c4 + 1) * PS + p] = v.y * sc_s[c4 + 1];
        in_s[(c4 + 2) * PS + p] = v.z * sc_s[c4 + 2];
        in_s[(c4 + 3) * PS + p] = v.w * sc_s[c4 + 3];
    }
    __syncthreads();
    float acc[4][4];
    gemv64<128, 4>(in_s, w_s, b_s, acc);
    int tx = t & 15, ty = t >> 4;
    #pragma unroll
    for (int i = 0; i < 4; i++) {
        int pix = base + ty * 4 + i;
        int hw = hw0 + ty * 4 + i;
        #pragma unroll
        for (int j = 0; j < 4; j++) {
            int oc = tx + 16 * j;
            float x3 = acc[i][j] * bt_s[oc];
            size_t src = (size_t)b * C0 * HW + (size_t)oc * HW + hw;
            g_ycat[(size_t)pix * DWC + oc]      = xl[src] + x3;
            g_ycat[(size_t)pix * DWC + 64 + oc] = xr[src] + x3;
        }
    }
}

// ---------------- LN2 + conv4 (128->128) + SimpleGate -> 64 ----------------
__global__ __launch_bounds__(256) void k_ln2_conv4_sg(const float* __restrict__ g2,
                                                      const float* __restrict__ w,
                                                      const float* __restrict__ bias) {
    float* in_s = smbuf;                 // 128*PS
    float* w_s  = in_s + 128 * PS;       // 128*129
    float* b_s  = w_s + 128 * 129;       // 128
    float* g_sm = b_s + 128;             // 128
    float* stat = g_sm + 128;            // 128
    float* red  = stat + 128;            // 512
    int t = threadIdx.x;
    int base = blockIdx.x * 64;
    load_weights<128>(w, w_s, 128);
    if (t < 128) { b_s[t] = bias[t]; g_sm[t] = g2[t]; }
    stage_nhwc<128>(g_ycat, in_s, base);
    __syncthreads();
    {
        int p = t & 63, part = t >> 6;
        float s1 = 0.f, s2 = 0.f;
        #pragma unroll
        for (int q = 0; q < 32; q++) {
            float v = in_s[(part * 32 + q) * PS + p];
            s1 += v; s2 += v * v;
        }
        red[part * 64 + p] = s1;
        red[256 + part * 64 + p] = s2;
    }
    __syncthreads();
    if (t < 64) {
        float s1 = red[t] + red[64 + t] + red[128 + t] + red[192 + t];
        float s2 = red[256 + t] + red[320 + t] + red[384 + t] + red[448 + t];
        float m = s1 * (1.f / 128.f);
        float var = s2 * (1.f / 128.f) - m * m;
        stat[t] = m;
        stat[64 + t] = rsqrtf(var + 1e-5f);
    }
    __syncthreads();
    #pragma unroll
    for (int r = 0; r < 32; r++) {
        int idx = r * 256 + t;
        int c = idx >> 6, p = idx & 63;
        in_s[c * PS + p] = (in_s[c * PS + p] - stat[p]) * stat[64 + p] * g_sm[c];
    }
    __syncthreads();
    float acc[4][8];
    gemv64<128, 8>(in_s, w_s, b_s, acc);
    int tx = t & 15, ty = t >> 4;
    #pragma unroll
    for (int i = 0; i < 4; i++) {
        int pix = base + ty * 4 + i;
        #pragma unroll
        for (int j = 0; j < 4; j++)
            g_feat[(size_t)pix * C0 + tx + 16 * j] = acc[i][j] * acc[i][j + 4];
    }
}

// ---------------- conv5 (64->64) + final residuals -> NCHW outputs ----------------
__global__ __launch_bounds__(256) void k_conv5_out(const float* __restrict__ w,
                                                   const float* __restrict__ bias,
                                                   const float* __restrict__ gamma,
                                                   float* __restrict__ out) {
    float* in_s = smbuf;                 // 64*PS
    float* w_s  = in_s + 64 * PS;        // 64*65
    float* b_s  = w_s + 64 * 65;         // 64
    float* gm_s = b_s + 64;              // 64
    int t = threadIdx.x;
    int base = blockIdx.x * 64;
    int b = base / HW, hw0 = base % HW;
    load_weights<64>(w, w_s, 64);
    if (t < 64) { b_s[t] = bias[t]; gm_s[t] = gamma[t]; }
    stage_nhwc<64>(g_feat, in_s, base);
    __syncthreads();
    float acc[4][4];
    gemv64<64, 4>(in_s, w_s, b_s, acc);
    int tx = t & 15, ty = t >> 4;
    #pragma unroll
    for (int i = 0; i < 4; i++) {
        int pix = base + ty * 4 + i;
        int hw = hw0 + ty * 4 + i;
        #pragma unroll
        for (int j = 0; j < 4; j++) {
            int oc = tx + 16 * j;
            float zg = acc[i][j] * gm_s[oc];
            size_t dst = (size_t)b * C0 * HW + (size_t)oc * HW + hw;
            out[dst]                 = g_ycat[(size_t)pix * DWC + oc]      + zg;
            out[(size_t)NOUT + dst]  = g_ycat[(size_t)pix * DWC + 64 + oc] + zg;
        }
    }
}

// ---------------- host launch ----------------
extern "C" void kernel_launch(void* const* d_in, const int* in_sizes, int n_in,
                              void* d_out, int out_size) {
    const float* x_l     = (const float*)d_in[0];
    const float* x_r     = (const float*)d_in[1];
    const float* ln1_g   = (const float*)d_in[2];
    const float* pw1_w   = (const float*)d_in[3];
    const float* pw1_b   = (const float*)d_in[4];
    const float* val_w   = (const float*)d_in[5];
    const float* val_b   = (const float*)d_in[6];
    const float* dwc_w   = (const float*)d_in[7];
    const float* dwc_b   = (const float*)d_in[8];
    const float* om_w    = (const float*)d_in[9];
    const float* om_b    = (const float*)d_in[10];
    const float* outp_w  = (const float*)d_in[11];
    const float* outp_b  = (const float*)d_in[12];
    const float* sca_w   = (const float*)d_in[13];
    const float* sca_b   = (const float*)d_in[14];
    const float* conv3_w = (const float*)d_in[15];
    const float* conv3_b = (const float*)d_in[16];
    const float* norm2_g = (const float*)d_in[17];
    const float* conv4_w = (const float*)d_in[18];
    const float* conv4_b = (const float*)d_in[19];
    const float* conv5_w = (const float*)d_in[20];
    const float* conv5_b = (const float*)d_in[21];
    const float* beta    = (const float*)d_in[22];
    const float* gamma   = (const float*)d_in[23];
    float* out = (float*)d_out;

    const int SM_LNPW1 = (64 * PS + 128 * 65 + 128 + 64 + 128 + 512) * 4;
    const int SM_VAL   = (128 * PS + 128 * 129 + 128) * 4;
    const int SM_OM    = (128 * PS + 112 * 129 + 112) * 4;
    const int SM_OUTP  = SM_VAL;
    const int SM_CONV3 = (128 * PS + 64 * 129 + 64 + 128 + 64) * 4;
    const int SM_LN2   = (128 * PS + 128 * 129 + 128 + 128 + 128 + 512) * 4;
    const int SM_CONV5 = (64 * PS + 64 * 65 + 64 + 64) * 4;

    cudaFuncSetAttribute(k_ln_pw1,       cudaFuncAttributeMaxDynamicSharedMemorySize, SM_LNPW1);
    cudaFuncSetAttribute(k_val,          cudaFuncAttributeMaxDynamicSharedMemorySize, SM_VAL);
    cudaFuncSetAttribute(k_om,           cudaFuncAttributeMaxDynamicSharedMemorySize, SM_OM);
    cudaFuncSetAttribute(k_outp_sg,      cudaFuncAttributeMaxDynamicSharedMemorySize, SM_OUTP);
    cudaFuncSetAttribute(k_conv3_res,    cudaFuncAttributeMaxDynamicSharedMemorySize, SM_CONV3);
    cudaFuncSetAttribute(k_ln2_conv4_sg, cudaFuncAttributeMaxDynamicSharedMemorySize, SM_LN2);
    cudaFuncSetAttribute(k_conv5_out,    cudaFuncAttributeMaxDynamicSharedMemorySize, SM_CONV5);

    const int NB = NPIX / 64;  // 800

    k_zero_vp<<<6561, 256>>>();

    for (int br = 0; br < 2; br++) {
        const float* x = br ? x_r : x_l;
        k_ln_pw1<<<NB, 256, SM_LNPW1>>>(x, ln1_g, pw1_w, pw1_b);
        k_val<<<NB, 256, SM_VAL>>>(val_w, val_b);
        k_dwc<<<NPIX * 32 / 256, 256>>>(dwc_w, dwc_b);
        k_om<<<NB, 256, SM_OM>>>(om_w, om_b);
        k_sample<<<NPIX / 2, 256>>>();
        k_outp_sg<<<NB, 256, SM_OUTP>>>(outp_w, outp_b, br);
    }

    k_pool1<<<400, 256>>>();
    k_pool_scale<<<1, 256>>>(sca_w, sca_b);
    k_conv3_res<<<NB, 256, SM_CONV3>>>(conv3_w, conv3_b, x_l, x_r, beta);
    k_ln2_conv4_sg<<<NB, 256, SM_LN2>>>(norm2_g, conv4_w, conv4_b);
    k_conv5_out<<<NB, 256, SM_CONV5>>>(conv5_w, conv5_b, gamma, out);
}